// round 2
// baseline (speedup 1.0000x reference)
#include <cuda_runtime.h>
#include <math.h>

// Problem shape (fixed by the dataset)
#define T_   2048
#define H_   2048
#define E_   8
#define I_   5632
#define GU_N (2 * I_)        // 11264
#define NROW (2 * T_)        // 4096 gathered rows (top_k = 2)

// ---------------- scratch (device globals; no runtime allocation) ----------
__device__ float g_gu[(size_t)NROW * GU_N];     // 184 MB: gathered x @ w13^T
__device__ float g_h [(size_t)NROW * I_];       //  92 MB: silu(g)*u
__device__ float g_part[2 * (size_t)T_ * H_];   //  33 MB: per-slot partial outputs
__device__ int   g_row_token[NROW];
__device__ float g_row_gate [NROW];
__device__ int   g_row_slot [NROW];
__device__ int   g_off[E_];
__device__ int   g_cnt[E_];

// ---------------- router: softmax/top2/renorm + expert-compacted lists -----
__global__ void router_kernel(const float* __restrict__ logits) {
    __shared__ int s_cnt[E_];
    __shared__ int s_cur[E_];
    int tid = threadIdx.x;
    if (tid < E_) s_cnt[tid] = 0;
    __syncthreads();

    for (int t = tid; t < T_; t += blockDim.x) {
        const float* l = logits + (size_t)t * E_;
        int i0 = 0; float v0 = l[0];
        #pragma unroll
        for (int e = 1; e < E_; e++) { float v = l[e]; if (v > v0) { v0 = v; i0 = e; } }
        int i1 = -1; float v1 = -INFINITY;
        #pragma unroll
        for (int e = 0; e < E_; e++) {
            if (e == i0) continue;
            float v = l[e]; if (v > v1) { v1 = v; i1 = e; }
        }
        atomicAdd(&s_cnt[i0], 1);
        atomicAdd(&s_cnt[i1], 1);
    }
    __syncthreads();
    if (tid == 0) {
        int off = 0;
        for (int e = 0; e < E_; e++) {
            g_off[e] = off; g_cnt[e] = s_cnt[e]; s_cur[e] = off; off += s_cnt[e];
        }
    }
    __syncthreads();

    for (int t = tid; t < T_; t += blockDim.x) {
        const float* l = logits + (size_t)t * E_;
        int i0 = 0; float v0 = l[0];
        #pragma unroll
        for (int e = 1; e < E_; e++) { float v = l[e]; if (v > v0) { v0 = v; i0 = e; } }
        int i1 = -1; float v1 = -INFINITY;
        #pragma unroll
        for (int e = 0; e < E_; e++) {
            if (e == i0) continue;
            float v = l[e]; if (v > v1) { v1 = v; i1 = e; }
        }
        // renormalized top-2 softmax: w1 = sigmoid(v1 - v0), w0 = 1 - w1
        float w1 = 1.0f / (1.0f + expf(v0 - v1));
        float w0 = 1.0f - w1;
        int p0 = atomicAdd(&s_cur[i0], 1);
        g_row_token[p0] = t; g_row_gate[p0] = w0; g_row_slot[p0] = 0;
        int p1 = atomicAdd(&s_cur[i1], 1);
        g_row_token[p1] = t; g_row_gate[p1] = w1; g_row_slot[p1] = 1;
    }
}

// ---------------- tiled TN GEMM config ------------------------------------
#define BM 128
#define BN 128
#define BK 8
#define PAD 4   // smem row pad: conflict-free stores, keeps 16B alignment

// GEMM1: gu[r, n] = sum_k X[token[r], k] * W13[e][n, k]   (K = H_ = 2048)
__global__ __launch_bounds__(256, 2)
void gemm1_kernel(const float* __restrict__ X, const float* __restrict__ W13) {
    int e   = blockIdx.z;
    int cnt = g_cnt[e];
    int m0  = blockIdx.y * BM;
    if (m0 >= cnt) return;
    int base = g_off[e];
    int n0   = blockIdx.x * BN;

    __shared__ float As[2][BK][BM + PAD];
    __shared__ float Bs[2][BK][BN + PAD];

    int tid  = threadIdx.x;
    int lrow = tid >> 1;            // 0..127
    int lk   = (tid & 1) * 4;       // 0 or 4

    int  am     = m0 + lrow;
    bool avalid = (am < cnt);
    int  token  = avalid ? g_row_token[base + am] : 0;
    const float* aptr = X + (size_t)token * H_ + lk;
    const float* bptr = W13 + ((size_t)e * GU_N + n0 + lrow) * (size_t)H_ + lk;

    float4 fa = avalid ? *(const float4*)aptr : make_float4(0.f, 0.f, 0.f, 0.f);
    float4 fb = *(const float4*)bptr;
    As[0][lk+0][lrow] = fa.x; As[0][lk+1][lrow] = fa.y;
    As[0][lk+2][lrow] = fa.z; As[0][lk+3][lrow] = fa.w;
    Bs[0][lk+0][lrow] = fb.x; Bs[0][lk+1][lrow] = fb.y;
    Bs[0][lk+2][lrow] = fb.z; Bs[0][lk+3][lrow] = fb.w;
    __syncthreads();

    float acc[8][8];
    #pragma unroll
    for (int i = 0; i < 8; i++)
        #pragma unroll
        for (int j = 0; j < 8; j++) acc[i][j] = 0.f;

    int ty = tid >> 4, tx = tid & 15;
    int mo = ty * 8, no = tx * 8;

    const int nK = H_ / BK;   // 256
    int buf = 0;
    for (int kt = 0; kt < nK; kt++) {
        if (kt + 1 < nK) {
            fa = avalid ? *(const float4*)(aptr + (kt + 1) * BK)
                        : make_float4(0.f, 0.f, 0.f, 0.f);
            fb = *(const float4*)(bptr + (kt + 1) * BK);
        }
        #pragma unroll
        for (int k = 0; k < BK; k++) {
            const float* ak = &As[buf][k][mo];
            const float* bk = &Bs[buf][k][no];
            float a[8], b[8];
            *(float4*)(a)     = *(const float4*)(ak);
            *(float4*)(a + 4) = *(const float4*)(ak + 4);
            *(float4*)(b)     = *(const float4*)(bk);
            *(float4*)(b + 4) = *(const float4*)(bk + 4);
            #pragma unroll
            for (int i = 0; i < 8; i++)
                #pragma unroll
                for (int j = 0; j < 8; j++)
                    acc[i][j] += a[i] * b[j];
        }
        if (kt + 1 < nK) {
            int nb = buf ^ 1;
            As[nb][lk+0][lrow] = fa.x; As[nb][lk+1][lrow] = fa.y;
            As[nb][lk+2][lrow] = fa.z; As[nb][lk+3][lrow] = fa.w;
            Bs[nb][lk+0][lrow] = fb.x; Bs[nb][lk+1][lrow] = fb.y;
            Bs[nb][lk+2][lrow] = fb.z; Bs[nb][lk+3][lrow] = fb.w;
        }
        __syncthreads();
        buf ^= 1;
    }

    #pragma unroll
    for (int i = 0; i < 8; i++) {
        int m = m0 + mo + i;
        if (m < cnt) {
            float* o = g_gu + (size_t)(base + m) * GU_N + n0 + no;
            *(float4*)(o)     = make_float4(acc[i][0], acc[i][1], acc[i][2], acc[i][3]);
            *(float4*)(o + 4) = make_float4(acc[i][4], acc[i][5], acc[i][6], acc[i][7]);
        }
    }
}

// ---------------- activation: h = silu(g) * u ------------------------------
__global__ void act_kernel() {
    int idx4 = blockIdx.x * blockDim.x + threadIdx.x;   // over NROW * I_ / 4
    if (idx4 >= NROW * (I_ / 4)) return;
    int r  = idx4 / (I_ / 4);
    int j4 = idx4 % (I_ / 4);
    const float4 g = *(const float4*)&g_gu[(size_t)r * GU_N + j4 * 4];
    const float4 u = *(const float4*)&g_gu[(size_t)r * GU_N + I_ + j4 * 4];
    float4 h;
    h.x = g.x / (1.f + expf(-g.x)) * u.x;
    h.y = g.y / (1.f + expf(-g.y)) * u.y;
    h.z = g.z / (1.f + expf(-g.z)) * u.z;
    h.w = g.w / (1.f + expf(-g.w)) * u.w;
    *(float4*)&g_h[(size_t)r * I_ + j4 * 4] = h;
}

// GEMM2: part[slot[r], token[r], n] = gate[r] * sum_k h[r,k] * W2[e][n,k]  (K = I_)
__global__ __launch_bounds__(256, 2)
void gemm2_kernel(const float* __restrict__ W2) {
    int e   = blockIdx.z;
    int cnt = g_cnt[e];
    int m0  = blockIdx.y * BM;
    if (m0 >= cnt) return;
    int base = g_off[e];
    int n0   = blockIdx.x * BN;

    __shared__ float As[2][BK][BM + PAD];
    __shared__ float Bs[2][BK][BN + PAD];

    int tid  = threadIdx.x;
    int lrow = tid >> 1;
    int lk   = (tid & 1) * 4;

    int  am     = m0 + lrow;
    bool avalid = (am < cnt);
    const float* aptr = g_h + (size_t)(base + (avalid ? am : 0)) * I_ + lk;
    const float* bptr = W2 + ((size_t)e * H_ + n0 + lrow) * (size_t)I_ + lk;

    float4 fa = avalid ? *(const float4*)aptr : make_float4(0.f, 0.f, 0.f, 0.f);
    float4 fb = *(const float4*)bptr;
    As[0][lk+0][lrow] = fa.x; As[0][lk+1][lrow] = fa.y;
    As[0][lk+2][lrow] = fa.z; As[0][lk+3][lrow] = fa.w;
    Bs[0][lk+0][lrow] = fb.x; Bs[0][lk+1][lrow] = fb.y;
    Bs[0][lk+2][lrow] = fb.z; Bs[0][lk+3][lrow] = fb.w;
    __syncthreads();

    float acc[8][8];
    #pragma unroll
    for (int i = 0; i < 8; i++)
        #pragma unroll
        for (int j = 0; j < 8; j++) acc[i][j] = 0.f;

    int ty = tid >> 4, tx = tid & 15;
    int mo = ty * 8, no = tx * 8;

    const int nK = I_ / BK;   // 704
    int buf = 0;
    for (int kt = 0; kt < nK; kt++) {
        if (kt + 1 < nK) {
            fa = avalid ? *(const float4*)(aptr + (kt + 1) * BK)
                        : make_float4(0.f, 0.f, 0.f, 0.f);
            fb = *(const float4*)(bptr + (kt + 1) * BK);
        }
        #pragma unroll
        for (int k = 0; k < BK; k++) {
            const float* ak = &As[buf][k][mo];
            const float* bk = &Bs[buf][k][no];
            float a[8], b[8];
            *(float4*)(a)     = *(const float4*)(ak);
            *(float4*)(a + 4) = *(const float4*)(ak + 4);
            *(float4*)(b)     = *(const float4*)(bk);
            *(float4*)(b + 4) = *(const float4*)(bk + 4);
            #pragma unroll
            for (int i = 0; i < 8; i++)
                #pragma unroll
                for (int j = 0; j < 8; j++)
                    acc[i][j] += a[i] * b[j];
        }
        if (kt + 1 < nK) {
            int nb = buf ^ 1;
            As[nb][lk+0][lrow] = fa.x; As[nb][lk+1][lrow] = fa.y;
            As[nb][lk+2][lrow] = fa.z; As[nb][lk+3][lrow] = fa.w;
            Bs[nb][lk+0][lrow] = fb.x; Bs[nb][lk+1][lrow] = fb.y;
            Bs[nb][lk+2][lrow] = fb.z; Bs[nb][lk+3][lrow] = fb.w;
        }
        __syncthreads();
        buf ^= 1;
    }

    #pragma unroll
    for (int i = 0; i < 8; i++) {
        int m = m0 + mo + i;
        if (m < cnt) {
            int   r    = base + m;
            float gate = g_row_gate[r];
            int   slot = g_row_slot[r];
            int   tok  = g_row_token[r];
            float* o = g_part + ((size_t)slot * T_ + tok) * H_ + n0 + no;
            *(float4*)(o)     = make_float4(gate * acc[i][0], gate * acc[i][1],
                                            gate * acc[i][2], gate * acc[i][3]);
            *(float4*)(o + 4) = make_float4(gate * acc[i][4], gate * acc[i][5],
                                            gate * acc[i][6], gate * acc[i][7]);
        }
    }
}

// ---------------- final: out = part[slot0] + part[slot1] -------------------
__global__ void add_kernel(float* __restrict__ out) {
    int idx4 = blockIdx.x * blockDim.x + threadIdx.x;   // over T_*H_/4
    if (idx4 >= T_ * (H_ / 4)) return;
    const float4 a = *(const float4*)&g_part[(size_t)idx4 * 4];
    const float4 b = *(const float4*)&g_part[(size_t)T_ * H_ + (size_t)idx4 * 4];
    float4 o;
    o.x = a.x + b.x; o.y = a.y + b.y; o.z = a.z + b.z; o.w = a.w + b.w;
    *(float4*)&out[(size_t)idx4 * 4] = o;
}

// ---------------- launch ----------------------------------------------------
extern "C" void kernel_launch(void* const* d_in, const int* in_sizes, int n_in,
                              void* d_out, int out_size) {
    const float* X      = (const float*)d_in[0];   // [T, H]
    const float* logits = (const float*)d_in[1];   // [T, E]
    const float* w13    = (const float*)d_in[2];   // [E, 2I, H]
    const float* w2     = (const float*)d_in[3];   // [E, H, I]
    float* out = (float*)d_out;

    router_kernel<<<1, 256>>>(logits);

    dim3 g1(GU_N / BN, T_ / BM, E_);     // (88, 16, 8); empty tiles exit early
    gemm1_kernel<<<g1, 256>>>(X, w13);

    int act_elems = NROW * (I_ / 4);
    act_kernel<<<(act_elems + 255) / 256, 256>>>();

    dim3 g2(H_ / BN, T_ / BM, E_);       // (16, 16, 8)
    gemm2_kernel<<<g2, 256>>>(w2);

    int add_elems = T_ * (H_ / 4);
    add_kernel<<<(add_elems + 255) / 256, 256>>>(out);
}

// round 5
// speedup vs baseline: 1.6812x; 1.6812x over previous
#include <cuda_runtime.h>
#include <math.h>
#include <stdint.h>

// Problem shape (fixed by the dataset)
#define T_   2048
#define H_   2048
#define E_   8
#define I_   5632
#define GU_N (2 * I_)        // 11264
#define NROW (2 * T_)        // 4096 gathered rows (top_k = 2)

// ---------------- scratch (device globals; no runtime allocation) ----------
__device__ float g_gu[(size_t)NROW * GU_N];     // gathered x @ w13^T
__device__ float g_h [(size_t)NROW * I_];       // silu(g)*u
__device__ float g_part[2 * (size_t)T_ * H_];   // per-slot partial outputs
__device__ int   g_row_token[NROW];
__device__ float g_row_gate [NROW];
__device__ int   g_row_slot [NROW];
__device__ int   g_off[E_];
__device__ int   g_cnt[E_];

// ---------------- helpers ---------------------------------------------------
__device__ __forceinline__ uint32_t smem_u32(const void* p) {
    uint32_t a;
    asm("{ .reg .u64 t; cvta.to.shared.u64 t, %1; cvt.u32.u64 %0, t; }"
        : "=r"(a) : "l"(p));
    return a;
}
__device__ __forceinline__ uint32_t lds32(uint32_t addr) {
    uint32_t v;
    asm volatile("ld.shared.b32 %0, [%1];" : "=r"(v) : "r"(addr));
    return v;
}
// bf16 mma: D(16x8) += A(16x16) * B(16x8), fp32 accum
__device__ __forceinline__ void mma16816(float c[4], const uint32_t a[4], const uint32_t b[2]) {
    asm volatile("mma.sync.aligned.m16n8k16.row.col.f32.bf16.bf16.f32 "
        "{%0,%1,%2,%3}, {%4,%5,%6,%7}, {%8,%9}, {%0,%1,%2,%3};"
        : "+f"(c[0]), "+f"(c[1]), "+f"(c[2]), "+f"(c[3])
        : "r"(a[0]), "r"(a[1]), "r"(a[2]), "r"(a[3]), "r"(b[0]), "r"(b[1]));
}
// fp32x4 -> bf16 hi/lo (2x b32 each), stored to smem
__device__ __forceinline__ void cvt_store4(float4 f, uint32_t hi_addr, uint32_t lo_addr) {
    uint32_t h01, h23, l01, l23;
    asm("cvt.rn.bf16x2.f32 %0, %1, %2;" : "=r"(h01) : "f"(f.y), "f"(f.x));
    asm("cvt.rn.bf16x2.f32 %0, %1, %2;" : "=r"(h23) : "f"(f.w), "f"(f.z));
    float hx = __uint_as_float(h01 << 16);
    float hy = __uint_as_float(h01 & 0xffff0000u);
    float hz = __uint_as_float(h23 << 16);
    float hw = __uint_as_float(h23 & 0xffff0000u);
    asm("cvt.rn.bf16x2.f32 %0, %1, %2;" : "=r"(l01) : "f"(f.y - hy), "f"(f.x - hx));
    asm("cvt.rn.bf16x2.f32 %0, %1, %2;" : "=r"(l23) : "f"(f.w - hw), "f"(f.z - hz));
    asm volatile("st.shared.v2.b32 [%0], {%1, %2};" :: "r"(hi_addr), "r"(h01), "r"(h23) : "memory");
    asm volatile("st.shared.v2.b32 [%0], {%1, %2};" :: "r"(lo_addr), "r"(l01), "r"(l23) : "memory");
}

// ---------------- router ----------------------------------------------------
__global__ void router_kernel(const float* __restrict__ logits) {
    __shared__ int s_cnt[E_];
    __shared__ int s_cur[E_];
    int tid = threadIdx.x;
    if (tid < E_) s_cnt[tid] = 0;
    __syncthreads();

    for (int t = tid; t < T_; t += blockDim.x) {
        const float* l = logits + (size_t)t * E_;
        int i0 = 0; float v0 = l[0];
        #pragma unroll
        for (int e = 1; e < E_; e++) { float v = l[e]; if (v > v0) { v0 = v; i0 = e; } }
        int i1 = -1; float v1 = -INFINITY;
        #pragma unroll
        for (int e = 0; e < E_; e++) {
            if (e == i0) continue;
            float v = l[e]; if (v > v1) { v1 = v; i1 = e; }
        }
        atomicAdd(&s_cnt[i0], 1);
        atomicAdd(&s_cnt[i1], 1);
    }
    __syncthreads();
    if (tid == 0) {
        int off = 0;
        for (int e = 0; e < E_; e++) {
            g_off[e] = off; g_cnt[e] = s_cnt[e]; s_cur[e] = off; off += s_cnt[e];
        }
    }
    __syncthreads();

    for (int t = tid; t < T_; t += blockDim.x) {
        const float* l = logits + (size_t)t * E_;
        int i0 = 0; float v0 = l[0];
        #pragma unroll
        for (int e = 1; e < E_; e++) { float v = l[e]; if (v > v0) { v0 = v; i0 = e; } }
        int i1 = -1; float v1 = -INFINITY;
        #pragma unroll
        for (int e = 0; e < E_; e++) {
            if (e == i0) continue;
            float v = l[e]; if (v > v1) { v1 = v; i1 = e; }
        }
        float w1 = 1.0f / (1.0f + expf(v0 - v1));
        float w0 = 1.0f - w1;
        int p0 = atomicAdd(&s_cur[i0], 1);
        g_row_token[p0] = t; g_row_gate[p0] = w0; g_row_slot[p0] = 0;
        int p1 = atomicAdd(&s_cur[i1], 1);
        g_row_token[p1] = t; g_row_gate[p1] = w1; g_row_slot[p1] = 1;
    }
}

// ---------------- HMMA grouped GEMM -----------------------------------------
// D[m, n] = sum_k A[m, k] * B_e[n, k], A fp32 split into bf16 hi+lo (3-pass).
// Tile 128x128, K-chunk 64 fp32. smem: per stage AHI/ALO/BHI/BLO 16KB each.
// SW128 swizzle: byte (row*128 + c*16 + w) stored at chunk c^(row&7).
template <int KDIM, int NTOT, bool GATHER, bool EPI2>
__global__ __launch_bounds__(256, 1)
void moe_gemm_mma(const float* __restrict__ Asrc, const float* __restrict__ Bsrc) {
    int e   = blockIdx.z;
    int cnt = g_cnt[e];
    int m0  = blockIdx.x * 128;          // x = m-tile: consecutive CTAs share B n-tile (L2)
    if (m0 >= cnt) return;
    int base = g_off[e];
    int n0   = blockIdx.y * 128;

    extern __shared__ char dsm[];
    uint32_t sb = (smem_u32(dsm) + 1023u) & ~1023u;
    const uint32_t STG = 65536u;         // per-stage bytes
    // stage layout: AHI 0, ALO 16K, BHI 32K, BLO 48K

    int tid  = threadIdx.x;
    int wid  = tid >> 5, lane = tid & 31;
    int wm   = wid & 1;                  // warp m-group (64 rows)
    int wn   = wid >> 1;                 // warp n-group (32 cols)
    int lr   = lane >> 2;                // 0..7
    uint32_t lc = (uint32_t)(lane & 3) * 4u;   // byte within 16B chunk

    // ---- loader mapping: 2 threads per row, 8 float4 each (64 floats/row)
    int r    = tid >> 1;                 // 0..127
    int q0   = (tid & 1) * 8;            // quad base within row

    bool av  = (m0 + r) < cnt;
    const float4* arow4;
    if (GATHER) {
        int tok = av ? g_row_token[base + m0 + r] : 0;
        arow4 = (const float4*)(Asrc + (size_t)tok * KDIM);
    } else {
        arow4 = (const float4*)(g_h + (size_t)(base + (av ? m0 + r : 0)) * KDIM);
    }
    const float4* brow4 = (const float4*)(Bsrc + ((size_t)e * NTOT + n0 + r) * (size_t)KDIM);

    // precomputed swizzled store offsets for the 8 quads of this thread's row
    uint32_t soff[8];
    #pragma unroll
    for (int q = 0; q < 8; q++) {
        int qi = q0 + q;
        soff[q] = (uint32_t)r * 128u + (uint32_t)(((qi >> 1) ^ (r & 7)) << 4) + (uint32_t)((qi & 1) * 8);
    }

    float acc[4][4][4];
    #pragma unroll
    for (int i = 0; i < 4; i++)
        #pragma unroll
        for (int j = 0; j < 4; j++)
            #pragma unroll
            for (int k = 0; k < 4; k++) acc[i][j][k] = 0.f;

    // ---- load chunk 0 into stage 0
    {
        uint32_t st = sb;
        #pragma unroll
        for (int q = 0; q < 8; q++) {
            float4 fa = av ? arow4[q0 + q] : make_float4(0.f, 0.f, 0.f, 0.f);
            cvt_store4(fa, st + soff[q], st + 16384u + soff[q]);
            float4 fb = brow4[q0 + q];
            cvt_store4(fb, st + 32768u + soff[q], st + 49152u + soff[q]);
        }
    }
    __syncthreads();

    const int nK = KDIM / 64;
    for (int kt = 0; kt < nK; kt++) {
        int cur = kt & 1, nxt = cur ^ 1;

        // prefetch next chunk into registers (overlaps with HMMA below)
        float4 pfa[8], pfb[8];
        if (kt + 1 < nK) {
            int kb = (kt + 1) * 16 + q0;
            #pragma unroll
            for (int q = 0; q < 8; q++) {
                pfa[q] = av ? arow4[kb + q] : make_float4(0.f, 0.f, 0.f, 0.f);
                pfb[q] = brow4[kb + q];
            }
        }

        // ---- compute chunk kt
        uint32_t st  = sb + (uint32_t)cur * STG;
        uint32_t AHI = st, ALO = st + 16384u, BHI = st + 32768u, BLO = st + 49152u;
        #pragma unroll
        for (int s = 0; s < 4; s++) {
            uint32_t c0 = (uint32_t)(s * 2);
            uint32_t bh[4][2], bl[4][2];
            #pragma unroll
            for (int nt = 0; nt < 4; nt++) {
                int n = wn * 32 + nt * 8 + lr;
                uint32_t rb = (uint32_t)n * 128u;
                uint32_t rx = (uint32_t)(n & 7);
                uint32_t o0 = rb + ((c0 ^ rx) << 4) + lc;
                uint32_t o1 = rb + (((c0 + 1) ^ rx) << 4) + lc;
                bh[nt][0] = lds32(BHI + o0); bh[nt][1] = lds32(BHI + o1);
                bl[nt][0] = lds32(BLO + o0); bl[nt][1] = lds32(BLO + o1);
            }
            #pragma unroll
            for (int mt = 0; mt < 4; mt++) {
                int r0 = wm * 64 + mt * 16 + lr;
                int r1 = r0 + 8;
                uint32_t rb0 = (uint32_t)r0 * 128u, rx0 = (uint32_t)(r0 & 7);
                uint32_t rb1 = (uint32_t)r1 * 128u, rx1 = (uint32_t)(r1 & 7);
                uint32_t oa0 = rb0 + ((c0 ^ rx0) << 4) + lc;
                uint32_t oa1 = rb1 + ((c0 ^ rx1) << 4) + lc;
                uint32_t oa2 = rb0 + (((c0 + 1) ^ rx0) << 4) + lc;
                uint32_t oa3 = rb1 + (((c0 + 1) ^ rx1) << 4) + lc;
                uint32_t ah[4] = { lds32(AHI + oa0), lds32(AHI + oa1),
                                   lds32(AHI + oa2), lds32(AHI + oa3) };
                uint32_t al[4] = { lds32(ALO + oa0), lds32(ALO + oa1),
                                   lds32(ALO + oa2), lds32(ALO + oa3) };
                #pragma unroll
                for (int nt = 0; nt < 4; nt++) {
                    mma16816(acc[mt][nt], ah, bh[nt]);   // hi*hi
                    mma16816(acc[mt][nt], ah, bl[nt]);   // hi*lo
                    mma16816(acc[mt][nt], al, bh[nt]);   // lo*hi
                }
            }
        }

        // ---- store prefetched chunk to the other stage
        if (kt + 1 < nK) {
            uint32_t st2 = sb + (uint32_t)nxt * STG;
            #pragma unroll
            for (int q = 0; q < 8; q++) {
                cvt_store4(pfa[q], st2 + soff[q], st2 + 16384u + soff[q]);
                cvt_store4(pfb[q], st2 + 32768u + soff[q], st2 + 49152u + soff[q]);
            }
        }
        __syncthreads();
    }

    // ---------------- epilogue (registers -> gmem, float2 per pair) ---------
    int nc = (lane & 3) * 2;   // col offset within 8-wide n-tile
    #pragma unroll
    for (int mt = 0; mt < 4; mt++) {
        #pragma unroll
        for (int rh = 0; rh < 2; rh++) {
            int m = m0 + wm * 64 + mt * 16 + rh * 8 + lr;
            if (m >= cnt) continue;
            if (!EPI2) {
                float* orow = g_gu + (size_t)(base + m) * GU_N + n0 + wn * 32;
                #pragma unroll
                for (int nt = 0; nt < 4; nt++) {
                    float2 v = make_float2(acc[mt][nt][rh * 2], acc[mt][nt][rh * 2 + 1]);
                    *(float2*)(orow + nt * 8 + nc) = v;
                }
            } else {
                int   ridx = base + m;
                float gate = g_row_gate[ridx];
                int   slot = g_row_slot[ridx];
                int   tok  = g_row_token[ridx];
                float* orow = g_part + ((size_t)slot * T_ + tok) * H_ + n0 + wn * 32;
                #pragma unroll
                for (int nt = 0; nt < 4; nt++) {
                    float2 v = make_float2(gate * acc[mt][nt][rh * 2],
                                           gate * acc[mt][nt][rh * 2 + 1]);
                    *(float2*)(orow + nt * 8 + nc) = v;
                }
            }
        }
    }
}

// ---------------- activation: h = silu(g) * u ------------------------------
__global__ void act_kernel() {
    int idx4 = blockIdx.x * blockDim.x + threadIdx.x;
    if (idx4 >= NROW * (I_ / 4)) return;
    int r  = idx4 / (I_ / 4);
    int j4 = idx4 % (I_ / 4);
    const float4 g = *(const float4*)&g_gu[(size_t)r * GU_N + j4 * 4];
    const float4 u = *(const float4*)&g_gu[(size_t)r * GU_N + I_ + j4 * 4];
    float4 h;
    h.x = g.x / (1.f + expf(-g.x)) * u.x;
    h.y = g.y / (1.f + expf(-g.y)) * u.y;
    h.z = g.z / (1.f + expf(-g.z)) * u.z;
    h.w = g.w / (1.f + expf(-g.w)) * u.w;
    *(float4*)&g_h[(size_t)r * I_ + j4 * 4] = h;
}

// ---------------- final: out = part[slot0] + part[slot1] -------------------
__global__ void add_kernel(float* __restrict__ out) {
    int idx4 = blockIdx.x * blockDim.x + threadIdx.x;
    if (idx4 >= T_ * (H_ / 4)) return;
    const float4 a = *(const float4*)&g_part[(size_t)idx4 * 4];
    const float4 b = *(const float4*)&g_part[(size_t)T_ * H_ + (size_t)idx4 * 4];
    float4 o;
    o.x = a.x + b.x; o.y = a.y + b.y; o.z = a.z + b.z; o.w = a.w + b.w;
    *(float4*)&out[(size_t)idx4 * 4] = o;
}

// ---------------- launch ----------------------------------------------------
extern "C" void kernel_launch(void* const* d_in, const int* in_sizes, int n_in,
                              void* d_out, int out_size) {
    const float* X      = (const float*)d_in[0];   // [T, H]
    const float* logits = (const float*)d_in[1];   // [T, E]
    const float* w13    = (const float*)d_in[2];   // [E, 2I, H]
    const float* w2     = (const float*)d_in[3];   // [E, H, I]
    float* out = (float*)d_out;

    const int SMEM_BYTES = 2 * 65536 + 1024;       // 132096
    cudaFuncSetAttribute(moe_gemm_mma<H_, GU_N, true,  false>,
                         cudaFuncAttributeMaxDynamicSharedMemorySize, SMEM_BYTES);
    cudaFuncSetAttribute(moe_gemm_mma<I_, H_,   false, true>,
                         cudaFuncAttributeMaxDynamicSharedMemorySize, SMEM_BYTES);

    router_kernel<<<1, 256>>>(logits);

    // x = m-tile (fast) so CTAs sharing a weight n-tile run concurrently (L2 reuse)
    dim3 g1(NROW / 128, GU_N / 128, E_);           // (32, 88, 8); empty tiles exit early
    moe_gemm_mma<H_, GU_N, true, false><<<g1, 256, SMEM_BYTES>>>(X, w13);

    int act_elems = NROW * (I_ / 4);
    act_kernel<<<(act_elems + 255) / 256, 256>>>();

    dim3 g2(NROW / 128, H_ / 128, E_);             // (32, 16, 8)
    moe_gemm_mma<I_, H_, false, true><<<g2, 256, SMEM_BYTES>>>(nullptr, w2);

    int add_elems = T_ * (H_ / 4);
    add_kernel<<<(add_elems + 255) / 256, 256>>>(out);
}

// round 10
// speedup vs baseline: 1.8770x; 1.1164x over previous
#include <cuda_runtime.h>
#include <math.h>
#include <stdint.h>

// Problem shape (fixed by the dataset)
#define T_   2048
#define H_   2048
#define E_   8
#define I_   5632
#define GU_N (2 * I_)        // 11264
#define NROW (2 * T_)        // 4096 gathered rows (top_k = 2)

// GEMM tiling: CTA 128x256, 8 warps of 64x64, K-chunk 64 fp32
#define KC   64
#define BM_  128
#define BN_  256

// ---------------- scratch (device globals; no runtime allocation) ----------
__device__ float g_gu[(size_t)NROW * GU_N];
__device__ float g_h [(size_t)NROW * I_];
__device__ float g_part[2 * (size_t)T_ * H_];
__device__ int   g_row_token[NROW];
__device__ float g_row_gate [NROW];
__device__ int   g_row_slot [NROW];
__device__ int   g_off[E_];
__device__ int   g_cnt[E_];

// ---------------- helpers ---------------------------------------------------
__device__ __forceinline__ uint32_t smem_u32(const void* p) {
    uint32_t a;
    asm("{ .reg .u64 t; cvta.to.shared.u64 t, %1; cvt.u32.u64 %0, t; }"
        : "=r"(a) : "l"(p));
    return a;
}
__device__ __forceinline__ float2 lds64(uint32_t addr) {
    float2 v;
    asm volatile("ld.shared.v2.f32 {%0,%1}, [%2];" : "=f"(v.x), "=f"(v.y) : "r"(addr));
    return v;
}
// fp32 pair -> bf16x2 hi + bf16x2 lo (lo = residual)
__device__ __forceinline__ void cvt2(float f0, float f1, uint32_t& h, uint32_t& l) {
    asm("cvt.rn.bf16x2.f32 %0, %1, %2;" : "=r"(h) : "f"(f1), "f"(f0));
    float g0 = __uint_as_float(h << 16);
    float g1 = __uint_as_float(h & 0xffff0000u);
    asm("cvt.rn.bf16x2.f32 %0, %1, %2;" : "=r"(l) : "f"(f1 - g1), "f"(f0 - g0));
}
__device__ __forceinline__ void mma16816(float c[4], const uint32_t a[4], const uint32_t b[2]) {
    asm volatile("mma.sync.aligned.m16n8k16.row.col.f32.bf16.bf16.f32 "
        "{%0,%1,%2,%3}, {%4,%5,%6,%7}, {%8,%9}, {%0,%1,%2,%3};"
        : "+f"(c[0]), "+f"(c[1]), "+f"(c[2]), "+f"(c[3])
        : "r"(a[0]), "r"(a[1]), "r"(a[2]), "r"(a[3]), "r"(b[0]), "r"(b[1]));
}
#define CPA(dst, src, sz) \
    asm volatile("cp.async.cg.shared.global [%0], [%1], 16, %2;" \
                 :: "r"(dst), "l"(src), "r"(sz) : "memory")
#define CPC()  asm volatile("cp.async.commit_group;" ::: "memory")
#define CPW1() asm volatile("cp.async.wait_group 1;" ::: "memory")
#define CPW0() asm volatile("cp.async.wait_group 0;" ::: "memory")

// fp32 smem addressing: row stride 256B (64 floats), 16B chunks XOR-swizzled by row&7
__device__ __forceinline__ uint32_t sw_addr(uint32_t basep, int row, int kf) {
    return basep + (uint32_t)row * 256u
         + (uint32_t)((((kf >> 2) ^ (row & 7)) << 4) + (kf & 3) * 4);
}

// ---------------- router ----------------------------------------------------
__global__ void router_kernel(const float* __restrict__ logits) {
    __shared__ int s_cnt[E_];
    __shared__ int s_cur[E_];
    int tid = threadIdx.x;
    if (tid < E_) s_cnt[tid] = 0;
    __syncthreads();

    for (int t = tid; t < T_; t += blockDim.x) {
        const float* l = logits + (size_t)t * E_;
        int i0 = 0; float v0 = l[0];
        #pragma unroll
        for (int e = 1; e < E_; e++) { float v = l[e]; if (v > v0) { v0 = v; i0 = e; } }
        int i1 = -1; float v1 = -INFINITY;
        #pragma unroll
        for (int e = 0; e < E_; e++) {
            if (e == i0) continue;
            float v = l[e]; if (v > v1) { v1 = v; i1 = e; }
        }
        atomicAdd(&s_cnt[i0], 1);
        atomicAdd(&s_cnt[i1], 1);
    }
    __syncthreads();
    if (tid == 0) {
        int off = 0;
        for (int e = 0; e < E_; e++) {
            g_off[e] = off; g_cnt[e] = s_cnt[e]; s_cur[e] = off; off += s_cnt[e];
        }
    }
    __syncthreads();

    for (int t = tid; t < T_; t += blockDim.x) {
        const float* l = logits + (size_t)t * E_;
        int i0 = 0; float v0 = l[0];
        #pragma unroll
        for (int e = 1; e < E_; e++) { float v = l[e]; if (v > v0) { v0 = v; i0 = e; } }
        int i1 = -1; float v1 = -INFINITY;
        #pragma unroll
        for (int e = 0; e < E_; e++) {
            if (e == i0) continue;
            float v = l[e]; if (v > v1) { v1 = v; i1 = e; }
        }
        float w1 = 1.0f / (1.0f + expf(v0 - v1));
        float w0 = 1.0f - w1;
        int p0 = atomicAdd(&s_cur[i0], 1);
        g_row_token[p0] = t; g_row_gate[p0] = w0; g_row_slot[p0] = 0;
        int p1 = atomicAdd(&s_cur[i1], 1);
        g_row_token[p1] = t; g_row_gate[p1] = w1; g_row_slot[p1] = 1;
    }
}

// ---------------- HMMA grouped GEMM (fp32-smem, cvt-on-load, 3-pass) --------
template <int KDIM, int NTOT, bool GATHER, bool EPI2>
__global__ __launch_bounds__(256, 1)
void moe_gemm_mma(const float* __restrict__ Asrc, const float* __restrict__ Bsrc) {
    int e   = blockIdx.z;
    int cnt = g_cnt[e];
    int m0  = blockIdx.x * BM_;
    if (m0 >= cnt) return;
    int base = g_off[e];
    int n0   = blockIdx.y * BN_;

    extern __shared__ char dsm[];
    uint32_t sb = (smem_u32(dsm) + 1023u) & ~1023u;
    const uint32_t STG = 98304u;       // per-stage: A fp32 32KB + B fp32 64KB

    int tid  = threadIdx.x;
    int wid  = tid >> 5, lane = tid & 31;
    int wm   = wid & 1;                // 64-row group
    int wn   = wid >> 1;               // 64-col group
    int lr   = lane >> 2;              // 0..7
    int kq   = (lane & 3) * 2;         // k pair base within k16

    // ---- loader mapping
    int ra = tid >> 1;                 // A row 0..127
    int qa = (tid & 1) * 8;            // A quad base (8 quads per thread)
    bool av = (m0 + ra) < cnt;
    uint32_t asz = av ? 16u : 0u;
    const float4* arow4;
    if (GATHER) {
        int tok = av ? g_row_token[base + m0 + ra] : 0;
        arow4 = (const float4*)(Asrc + (size_t)tok * KDIM);
    } else {
        arow4 = (const float4*)(g_h + (size_t)(base + (av ? m0 + ra : 0)) * KDIM);
    }
    const float4* brow4 = (const float4*)(Bsrc + ((size_t)e * NTOT + n0 + tid) * (size_t)KDIM);

    // precomputed swizzled dst offsets
    uint32_t adst[8], bdst[16];
    #pragma unroll
    for (int q = 0; q < 8; q++)
        adst[q] = (uint32_t)ra * 256u + (uint32_t)(((qa + q) ^ (ra & 7)) << 4);
    #pragma unroll
    for (int q = 0; q < 16; q++)
        bdst[q] = 32768u + (uint32_t)tid * 256u + (uint32_t)((q ^ (tid & 7)) << 4);

    auto issue_chunk = [&](int kt, int st) {
        uint32_t stb = sb + (uint32_t)st * STG;
        int kb = kt * 16;
        #pragma unroll
        for (int q = 0; q < 8; q++)
            CPA(stb + adst[q], arow4 + kb + qa + q, asz);
        #pragma unroll
        for (int q = 0; q < 16; q++)
            CPA(stb + bdst[q], brow4 + kb + q, 16u);
        CPC();
    };

    float acc[4][8][4];
    #pragma unroll
    for (int i = 0; i < 4; i++)
        #pragma unroll
        for (int j = 0; j < 8; j++)
            #pragma unroll
            for (int k = 0; k < 4; k++) acc[i][j][k] = 0.f;

    const int nK = KDIM / KC;
    issue_chunk(0, 0);
    issue_chunk(1, 1);

    for (int kt = 0; kt < nK; kt++) {
        if (kt + 1 < nK) { CPW1(); } else { CPW0(); }
        __syncthreads();

        uint32_t stb = sb + (uint32_t)(kt & 1) * STG;
        uint32_t Ab  = stb;
        uint32_t Bb  = stb + 32768u;

        #pragma unroll
        for (int s = 0; s < 4; s++) {
            int k0 = s * 16 + kq;       // fp32 k of low pair
            int k1 = k0 + 8;

            uint32_t bh[8][2], bl[8][2];
            #pragma unroll
            for (int nt = 0; nt < 8; nt++) {
                int n = wn * 64 + nt * 8 + lr;
                float2 p0 = lds64(sw_addr(Bb, n, k0));
                float2 p1 = lds64(sw_addr(Bb, n, k1));
                cvt2(p0.x, p0.y, bh[nt][0], bl[nt][0]);
                cvt2(p1.x, p1.y, bh[nt][1], bl[nt][1]);
            }
            #pragma unroll
            for (int mt = 0; mt < 4; mt++) {
                int r0 = wm * 64 + mt * 16 + lr;
                int r1 = r0 + 8;
                float2 a00 = lds64(sw_addr(Ab, r0, k0));
                float2 a10 = lds64(sw_addr(Ab, r1, k0));
                float2 a01 = lds64(sw_addr(Ab, r0, k1));
                float2 a11 = lds64(sw_addr(Ab, r1, k1));
                uint32_t ah[4], al[4];
                cvt2(a00.x, a00.y, ah[0], al[0]);
                cvt2(a10.x, a10.y, ah[1], al[1]);
                cvt2(a01.x, a01.y, ah[2], al[2]);
                cvt2(a11.x, a11.y, ah[3], al[3]);
                // 3-pass, chains separated by 8 independent tiles
                #pragma unroll
                for (int nt = 0; nt < 8; nt++) mma16816(acc[mt][nt], ah, bh[nt]);
                #pragma unroll
                for (int nt = 0; nt < 8; nt++) mma16816(acc[mt][nt], ah, bl[nt]);
                #pragma unroll
                for (int nt = 0; nt < 8; nt++) mma16816(acc[mt][nt], al, bh[nt]);
            }
        }
        __syncthreads();
        if (kt + 2 < nK) issue_chunk(kt + 2, kt & 1);
    }

    // ---------------- epilogue ----------------
    int nc = (lane & 3) * 2;
    #pragma unroll
    for (int mt = 0; mt < 4; mt++) {
        #pragma unroll
        for (int rh = 0; rh < 2; rh++) {
            int m = m0 + wm * 64 + mt * 16 + rh * 8 + lr;
            if (m >= cnt) continue;
            if (!EPI2) {
                float* orow = g_gu + (size_t)(base + m) * GU_N + n0 + wn * 64;
                #pragma unroll
                for (int nt = 0; nt < 8; nt++) {
                    float2 v = make_float2(acc[mt][nt][rh * 2], acc[mt][nt][rh * 2 + 1]);
                    *(float2*)(orow + nt * 8 + nc) = v;
                }
            } else {
                int   ridx = base + m;
                float gate = g_row_gate[ridx];
                int   slot = g_row_slot[ridx];
                int   tok  = g_row_token[ridx];
                float* orow = g_part + ((size_t)slot * T_ + tok) * H_ + n0 + wn * 64;
                #pragma unroll
                for (int nt = 0; nt < 8; nt++) {
                    float2 v = make_float2(gate * acc[mt][nt][rh * 2],
                                           gate * acc[mt][nt][rh * 2 + 1]);
                    *(float2*)(orow + nt * 8 + nc) = v;
                }
            }
        }
    }
}

// ---------------- activation: h = silu(g) * u ------------------------------
__global__ void act_kernel() {
    int idx4 = blockIdx.x * blockDim.x + threadIdx.x;
    if (idx4 >= NROW * (I_ / 4)) return;
    int r  = idx4 / (I_ / 4);
    int j4 = idx4 % (I_ / 4);
    const float4 g = *(const float4*)&g_gu[(size_t)r * GU_N + j4 * 4];
    const float4 u = *(const float4*)&g_gu[(size_t)r * GU_N + I_ + j4 * 4];
    float4 h;
    h.x = g.x / (1.f + expf(-g.x)) * u.x;
    h.y = g.y / (1.f + expf(-g.y)) * u.y;
    h.z = g.z / (1.f + expf(-g.z)) * u.z;
    h.w = g.w / (1.f + expf(-g.w)) * u.w;
    *(float4*)&g_h[(size_t)r * I_ + j4 * 4] = h;
}

// ---------------- final: out = part[slot0] + part[slot1] -------------------
__global__ void add_kernel(float* __restrict__ out) {
    int idx4 = blockIdx.x * blockDim.x + threadIdx.x;
    if (idx4 >= T_ * (H_ / 4)) return;
    const float4 a = *(const float4*)&g_part[(size_t)idx4 * 4];
    const float4 b = *(const float4*)&g_part[(size_t)T_ * H_ + (size_t)idx4 * 4];
    float4 o;
    o.x = a.x + b.x; o.y = a.y + b.y; o.z = a.z + b.z; o.w = a.w + b.w;
    *(float4*)&out[(size_t)idx4 * 4] = o;
}

// ---------------- launch ----------------------------------------------------
extern "C" void kernel_launch(void* const* d_in, const int* in_sizes, int n_in,
                              void* d_out, int out_size) {
    const float* X      = (const float*)d_in[0];   // [T, H]
    const float* logits = (const float*)d_in[1];   // [T, E]
    const float* w13    = (const float*)d_in[2];   // [E, 2I, H]
    const float* w2     = (const float*)d_in[3];   // [E, H, I]
    float* out = (float*)d_out;

    const int SMEM_BYTES = 2 * 98304 + 1024;       // 197632
    cudaFuncSetAttribute(moe_gemm_mma<H_, GU_N, true,  false>,
                         cudaFuncAttributeMaxDynamicSharedMemorySize, SMEM_BYTES);
    cudaFuncSetAttribute(moe_gemm_mma<I_, H_,   false, true>,
                         cudaFuncAttributeMaxDynamicSharedMemorySize, SMEM_BYTES);

    router_kernel<<<1, 256>>>(logits);

    dim3 g1(NROW / BM_, GU_N / BN_, E_);           // (32, 44, 8)
    moe_gemm_mma<H_, GU_N, true, false><<<g1, 256, SMEM_BYTES>>>(X, w13);

    int act_elems = NROW * (I_ / 4);
    act_kernel<<<(act_elems + 255) / 256, 256>>>();

    dim3 g2(NROW / BM_, H_ / BN_, E_);             // (32, 8, 8)
    moe_gemm_mma<I_, H_, false, true><<<g2, 256, SMEM_BYTES>>>(nullptr, w2);

    int add_elems = T_ * (H_ / 4);
    add_kernel<<<(add_elems + 255) / 256, 256>>>(out);
}

// round 12
// speedup vs baseline: 2.3453x; 1.2495x over previous
#include <cuda_runtime.h>
#include <math.h>
#include <stdint.h>

// Problem shape (fixed by the dataset)
#define T_   2048
#define H_   2048
#define E_   8
#define I_   5632
#define GU_N (2 * I_)        // 11264
#define NROW (2 * T_)        // 4096 gathered rows (top_k = 2)

// GEMM tiling: CTA 128x128, 8 warps of 64x32, K-chunk 32 fp32, 3-stage pipe
#define KC   32
#define BM_  128
#define BN_  128
#define NSTG 3
#define STGB 32768u          // per-stage: A 16KB + B 16KB

// ---------------- scratch (device globals; no runtime allocation) ----------
__device__ float g_gu[(size_t)NROW * GU_N];
__device__ float g_h [(size_t)NROW * I_];
__device__ float g_part[2 * (size_t)T_ * H_];
__device__ int   g_row_token[NROW];
__device__ float g_row_gate [NROW];
__device__ int   g_row_slot [NROW];
__device__ int   g_off[E_];
__device__ int   g_cnt[E_];

// ---------------- helpers ---------------------------------------------------
__device__ __forceinline__ uint32_t smem_u32(const void* p) {
    uint32_t a;
    asm("{ .reg .u64 t; cvta.to.shared.u64 t, %1; cvt.u32.u64 %0, t; }"
        : "=r"(a) : "l"(p));
    return a;
}
__device__ __forceinline__ float2 lds64(uint32_t addr) {
    float2 v;
    asm volatile("ld.shared.v2.f32 {%0,%1}, [%2];" : "=f"(v.x), "=f"(v.y) : "r"(addr));
    return v;
}
// fp32 pair -> bf16x2 hi + bf16x2 lo (lo = residual)
__device__ __forceinline__ void cvt2(float f0, float f1, uint32_t& h, uint32_t& l) {
    asm("cvt.rn.bf16x2.f32 %0, %1, %2;" : "=r"(h) : "f"(f1), "f"(f0));
    float g0 = __uint_as_float(h << 16);
    float g1 = __uint_as_float(h & 0xffff0000u);
    asm("cvt.rn.bf16x2.f32 %0, %1, %2;" : "=r"(l) : "f"(f1 - g1), "f"(f0 - g0));
}
__device__ __forceinline__ void mma16816(float c[4], const uint32_t a[4], const uint32_t b[2]) {
    asm volatile("mma.sync.aligned.m16n8k16.row.col.f32.bf16.bf16.f32 "
        "{%0,%1,%2,%3}, {%4,%5,%6,%7}, {%8,%9}, {%0,%1,%2,%3};"
        : "+f"(c[0]), "+f"(c[1]), "+f"(c[2]), "+f"(c[3])
        : "r"(a[0]), "r"(a[1]), "r"(a[2]), "r"(a[3]), "r"(b[0]), "r"(b[1]));
}
#define CPA(dst, src, sz) \
    asm volatile("cp.async.cg.shared.global [%0], [%1], 16, %2;" \
                 :: "r"(dst), "l"(src), "r"(sz) : "memory")
#define CPC()  asm volatile("cp.async.commit_group;" ::: "memory")
#define CPW2() asm volatile("cp.async.wait_group 2;" ::: "memory")
#define CPW0() asm volatile("cp.async.wait_group 0;" ::: "memory")

// fp32 smem addressing: row stride 128B (32 floats), 16B chunks XOR-swizzled by row&7
__device__ __forceinline__ uint32_t sw_addr(uint32_t basep, int row, int kf) {
    return basep + (uint32_t)row * 128u
         + (uint32_t)((((kf >> 2) ^ (row & 7)) << 4) + (kf & 3) * 4);
}

// ---------------- router ----------------------------------------------------
__global__ void router_kernel(const float* __restrict__ logits) {
    __shared__ int s_cnt[E_];
    __shared__ int s_cur[E_];
    int tid = threadIdx.x;
    if (tid < E_) s_cnt[tid] = 0;
    __syncthreads();

    for (int t = tid; t < T_; t += blockDim.x) {
        const float* l = logits + (size_t)t * E_;
        int i0 = 0; float v0 = l[0];
        #pragma unroll
        for (int e = 1; e < E_; e++) { float v = l[e]; if (v > v0) { v0 = v; i0 = e; } }
        int i1 = -1; float v1 = -INFINITY;
        #pragma unroll
        for (int e = 0; e < E_; e++) {
            if (e == i0) continue;
            float v = l[e]; if (v > v1) { v1 = v; i1 = e; }
        }
        atomicAdd(&s_cnt[i0], 1);
        atomicAdd(&s_cnt[i1], 1);
    }
    __syncthreads();
    if (tid == 0) {
        int off = 0;
        for (int e = 0; e < E_; e++) {
            g_off[e] = off; g_cnt[e] = s_cnt[e]; s_cur[e] = off; off += s_cnt[e];
        }
    }
    __syncthreads();

    for (int t = tid; t < T_; t += blockDim.x) {
        const float* l = logits + (size_t)t * E_;
        int i0 = 0; float v0 = l[0];
        #pragma unroll
        for (int e = 1; e < E_; e++) { float v = l[e]; if (v > v0) { v0 = v; i0 = e; } }
        int i1 = -1; float v1 = -INFINITY;
        #pragma unroll
        for (int e = 0; e < E_; e++) {
            if (e == i0) continue;
            float v = l[e]; if (v > v1) { v1 = v; i1 = e; }
        }
        float w1 = 1.0f / (1.0f + expf(v0 - v1));
        float w0 = 1.0f - w1;
        int p0 = atomicAdd(&s_cur[i0], 1);
        g_row_token[p0] = t; g_row_gate[p0] = w0; g_row_slot[p0] = 0;
        int p1 = atomicAdd(&s_cur[i1], 1);
        g_row_token[p1] = t; g_row_gate[p1] = w1; g_row_slot[p1] = 1;
    }
}

// ---------------- HMMA grouped GEMM (occ=2, 3-stage, cvt-on-load, 3-pass) ---
template <int KDIM, int NTOT, bool GATHER, bool EPI2>
__global__ __launch_bounds__(256, 2)
void moe_gemm_mma(const float* __restrict__ Asrc, const float* __restrict__ Bsrc) {
    int e   = blockIdx.z;
    int cnt = g_cnt[e];
    int m0  = blockIdx.x * BM_;
    if (m0 >= cnt) return;
    int base = g_off[e];
    int n0   = blockIdx.y * BN_;

    extern __shared__ char dsm[];
    uint32_t sb = (smem_u32(dsm) + 1023u) & ~1023u;

    int tid  = threadIdx.x;
    int wid  = tid >> 5, lane = tid & 31;
    int wm   = wid & 1;                // 64-row group
    int wn   = wid >> 1;               // 32-col group (0..3)
    int lr   = lane >> 2;              // 0..7
    int kq   = (lane & 3) * 2;         // k pair base within k16

    // ---- loader mapping: 2 threads per row, 4 float4 each (32 floats/row)
    int ra = tid >> 1;                 // row 0..127 (A rows and B rows)
    int qa = (tid & 1) * 4;            // quad base
    bool av = (m0 + ra) < cnt;
    uint32_t asz = av ? 16u : 0u;
    const float4* arow4;
    if (GATHER) {
        int tok = av ? g_row_token[base + m0 + ra] : 0;
        arow4 = (const float4*)(Asrc + (size_t)tok * KDIM);
    } else {
        arow4 = (const float4*)(g_h + (size_t)(base + (av ? m0 + ra : 0)) * KDIM);
    }
    const float4* brow4 = (const float4*)(Bsrc + ((size_t)e * NTOT + n0 + ra) * (size_t)KDIM);

    // precomputed swizzled dst offsets (A at 0, B at 16KB within stage)
    uint32_t adst[4], bdst[4];
    #pragma unroll
    for (int q = 0; q < 4; q++) {
        adst[q] = (uint32_t)ra * 128u + (uint32_t)(((qa + q) ^ (ra & 7)) << 4);
        bdst[q] = 16384u + adst[q];
    }

    auto issue_chunk = [&](int kt, int st) {
        uint32_t stb = sb + (uint32_t)st * STGB;
        int kb = kt * 8;               // 8 float4 per row per chunk
        #pragma unroll
        for (int q = 0; q < 4; q++)
            CPA(stb + adst[q], arow4 + kb + qa + q, asz);
        #pragma unroll
        for (int q = 0; q < 4; q++)
            CPA(stb + bdst[q], brow4 + kb + qa + q, 16u);
        CPC();
    };

    float acc[4][4][4];
    #pragma unroll
    for (int i = 0; i < 4; i++)
        #pragma unroll
        for (int j = 0; j < 4; j++)
            #pragma unroll
            for (int k = 0; k < 4; k++) acc[i][j][k] = 0.f;

    const int nK = KDIM / KC;
    issue_chunk(0, 0);
    issue_chunk(1, 1);
    issue_chunk(2, 2);

    int st = 0;
    for (int kt = 0; kt < nK; kt++) {
        if (kt + 2 < nK) { CPW2(); } else { CPW0(); }
        __syncthreads();

        uint32_t stb = sb + (uint32_t)st * STGB;
        uint32_t Ab  = stb;
        uint32_t Bb  = stb + 16384u;

        #pragma unroll
        for (int s = 0; s < 2; s++) {
            int k0 = s * 16 + kq;
            int k1 = k0 + 8;

            uint32_t bh[4][2], bl[4][2];
            #pragma unroll
            for (int nt = 0; nt < 4; nt++) {
                int n = wn * 32 + nt * 8 + lr;
                float2 p0 = lds64(sw_addr(Bb, n, k0));
                float2 p1 = lds64(sw_addr(Bb, n, k1));
                cvt2(p0.x, p0.y, bh[nt][0], bl[nt][0]);
                cvt2(p1.x, p1.y, bh[nt][1], bl[nt][1]);
            }
            #pragma unroll
            for (int mt = 0; mt < 4; mt++) {
                int r0 = wm * 64 + mt * 16 + lr;
                int r1 = r0 + 8;
                float2 a00 = lds64(sw_addr(Ab, r0, k0));
                float2 a10 = lds64(sw_addr(Ab, r1, k0));
                float2 a01 = lds64(sw_addr(Ab, r0, k1));
                float2 a11 = lds64(sw_addr(Ab, r1, k1));
                uint32_t ah[4], al[4];
                cvt2(a00.x, a00.y, ah[0], al[0]);
                cvt2(a10.x, a10.y, ah[1], al[1]);
                cvt2(a01.x, a01.y, ah[2], al[2]);
                cvt2(a11.x, a11.y, ah[3], al[3]);
                #pragma unroll
                for (int nt = 0; nt < 4; nt++) mma16816(acc[mt][nt], ah, bh[nt]);
                #pragma unroll
                for (int nt = 0; nt < 4; nt++) mma16816(acc[mt][nt], ah, bl[nt]);
                #pragma unroll
                for (int nt = 0; nt < 4; nt++) mma16816(acc[mt][nt], al, bh[nt]);
            }
        }
        __syncthreads();
        if (kt + 3 < nK) issue_chunk(kt + 3, st);
        st = (st + 1 == NSTG) ? 0 : st + 1;
    }

    // ---------------- epilogue ----------------
    int nc = (lane & 3) * 2;
    #pragma unroll
    for (int mt = 0; mt < 4; mt++) {
        #pragma unroll
        for (int rh = 0; rh < 2; rh++) {
            int m = m0 + wm * 64 + mt * 16 + rh * 8 + lr;
            if (m >= cnt) continue;
            if (!EPI2) {
                float* orow = g_gu + (size_t)(base + m) * GU_N + n0 + wn * 32;
                #pragma unroll
                for (int nt = 0; nt < 4; nt++) {
                    float2 v = make_float2(acc[mt][nt][rh * 2], acc[mt][nt][rh * 2 + 1]);
                    *(float2*)(orow + nt * 8 + nc) = v;
                }
            } else {
                int   ridx = base + m;
                float gate = g_row_gate[ridx];
                int   slot = g_row_slot[ridx];
                int   tok  = g_row_token[ridx];
                float* orow = g_part + ((size_t)slot * T_ + tok) * H_ + n0 + wn * 32;
                #pragma unroll
                for (int nt = 0; nt < 4; nt++) {
                    float2 v = make_float2(gate * acc[mt][nt][rh * 2],
                                           gate * acc[mt][nt][rh * 2 + 1]);
                    *(float2*)(orow + nt * 8 + nc) = v;
                }
            }
        }
    }
}

// ---------------- activation: h = silu(g) * u ------------------------------
__global__ void act_kernel() {
    int idx4 = blockIdx.x * blockDim.x + threadIdx.x;
    if (idx4 >= NROW * (I_ / 4)) return;
    int r  = idx4 / (I_ / 4);
    int j4 = idx4 % (I_ / 4);
    const float4 g = *(const float4*)&g_gu[(size_t)r * GU_N + j4 * 4];
    const float4 u = *(const float4*)&g_gu[(size_t)r * GU_N + I_ + j4 * 4];
    float4 h;
    h.x = g.x / (1.f + expf(-g.x)) * u.x;
    h.y = g.y / (1.f + expf(-g.y)) * u.y;
    h.z = g.z / (1.f + expf(-g.z)) * u.z;
    h.w = g.w / (1.f + expf(-g.w)) * u.w;
    *(float4*)&g_h[(size_t)r * I_ + j4 * 4] = h;
}

// ---------------- final: out = part[slot0] + part[slot1] -------------------
__global__ void add_kernel(float* __restrict__ out) {
    int idx4 = blockIdx.x * blockDim.x + threadIdx.x;
    if (idx4 >= T_ * (H_ / 4)) return;
    const float4 a = *(const float4*)&g_part[(size_t)idx4 * 4];
    const float4 b = *(const float4*)&g_part[(size_t)T_ * H_ + (size_t)idx4 * 4];
    float4 o;
    o.x = a.x + b.x; o.y = a.y + b.y; o.z = a.z + b.z; o.w = a.w + b.w;
    *(float4*)&out[(size_t)idx4 * 4] = o;
}

// ---------------- launch ----------------------------------------------------
extern "C" void kernel_launch(void* const* d_in, const int* in_sizes, int n_in,
                              void* d_out, int out_size) {
    const float* X      = (const float*)d_in[0];   // [T, H]
    const float* logits = (const float*)d_in[1];   // [T, E]
    const float* w13    = (const float*)d_in[2];   // [E, 2I, H]
    const float* w2     = (const float*)d_in[3];   // [E, H, I]
    float* out = (float*)d_out;

    const int SMEM_BYTES = NSTG * 32768 + 1024;    // 99328; 2 CTAs/SM -> 192KB+pad
    cudaFuncSetAttribute(moe_gemm_mma<H_, GU_N, true,  false>,
                         cudaFuncAttributeMaxDynamicSharedMemorySize, SMEM_BYTES);
    cudaFuncSetAttribute(moe_gemm_mma<I_, H_,   false, true>,
                         cudaFuncAttributeMaxDynamicSharedMemorySize, SMEM_BYTES);

    router_kernel<<<1, 256>>>(logits);

    dim3 g1(NROW / BM_, GU_N / BN_, E_);           // (32, 88, 8)
    moe_gemm_mma<H_, GU_N, true, false><<<g1, 256, SMEM_BYTES>>>(X, w13);

    int act_elems = NROW * (I_ / 4);
    act_kernel<<<(act_elems + 255) / 256, 256>>>();

    dim3 g2(NROW / BM_, H_ / BN_, E_);             // (32, 16, 8)
    moe_gemm_mma<I_, H_, false, true><<<g2, 256, SMEM_BYTES>>>(nullptr, w2);

    int add_elems = T_ * (H_ / 4);
    add_kernel<<<(add_elems + 255) / 256, 256>>>(out);
}